// round 15
// baseline (speedup 1.0000x reference)
#include <cuda_runtime.h>
#include <cuda_fp16.h>
#include <math.h>
#include <stdint.h>

// ---------------------------------------------------------------------------
// BidirectionalMamba: D=1024, E=2048, N=16, dt_rank=64, B=4, L=2048.
// fwd: causal conv + forward scan.  bwd: anti-causal conv + backward scan.
// GEMMs: 1-term fp16 (fp32 accum).  conv emits fp16 xi only; scan reads
// fp16 u and fuses the output gating.  delta stays on the FFMA pipe (K=64
// GEMM is latency-bound on tensor cores - measured R13 regression).
// ---------------------------------------------------------------------------
#define D_MODEL  1024
#define E_DIM    2048
#define FOUR_E   4096
#define EIGHT_E  8192
#define N_ST     16
#define DT_RANK  64
#define PROJ_N   96
#define B_SZ     4
#define L_SEQ    2048
#define M_ROWS   8192

__device__ float g_xz[(size_t)M_ROWS * EIGHT_E];
__device__ float g_delta[(size_t)M_ROWS * FOUR_E];
__device__ float g_proj[(size_t)2 * M_ROWS * PROJ_N];

__device__ __half g_xhi[(size_t)M_ROWS * D_MODEL];
__device__ __half g_xihi[(size_t)M_ROWS * FOUR_E];
__device__ __half g_yhi[(size_t)M_ROWS * FOUR_E];
__device__ __half g_btin[(size_t)EIGHT_E * D_MODEL];
__device__ __half g_btxp[(size_t)2 * 128 * E_DIM];
__device__ __half g_btout[(size_t)D_MODEL * FOUR_E];

// ---------------------------------------------------------------------------
// helpers
// ---------------------------------------------------------------------------
__device__ __forceinline__ uint32_t smem_to_u32(const void* p)
{
    uint32_t a;
    asm("{ .reg .u64 t; cvta.to.shared.u64 t, %1; cvt.u32.u64 %0, t; }" : "=r"(a) : "l"(p));
    return a;
}

#define LDSM_X4(r, a) \
    asm volatile("ldmatrix.sync.aligned.m8n8.x4.shared.b16 {%0,%1,%2,%3}, [%4];" \
        : "=r"((r)[0]), "=r"((r)[1]), "=r"((r)[2]), "=r"((r)[3]) : "r"(a))

__device__ __forceinline__ void mma16816(float* d, const uint32_t* a, const uint32_t* b)
{
    asm volatile(
        "mma.sync.aligned.m16n8k16.row.col.f32.f16.f16.f32 "
        "{%0,%1,%2,%3}, {%4,%5,%6,%7}, {%8,%9}, {%0,%1,%2,%3};"
        : "+f"(d[0]), "+f"(d[1]), "+f"(d[2]), "+f"(d[3])
        : "r"(a[0]), "r"(a[1]), "r"(a[2]), "r"(a[3]), "r"(b[0]), "r"(b[1]));
}

#define CP_ASYNC16(dst, src) \
    asm volatile("cp.async.cg.shared.global [%0], [%1], 16;" :: "r"(dst), "l"(src))
#define CP_COMMIT()  asm volatile("cp.async.commit_group;" ::: "memory")
#define CP_WAIT(n)   asm volatile("cp.async.wait_group %0;" :: "n"(n) : "memory")

// ---------------------------------------------------------------------------
// fp16 HMMA GEMM: C[M,N] = A[M,K] @ W[K,N]  (B = W^T, fp16).
// 128x128 tile, BK=64, 8 warps (2x4), warp 64x32, 3-stage cp.async ring,
// one barrier per k-tile, loads into slot+2.  Row pitch 144B keeps LDSM
// conflict-free.  2 CTAs/SM.  blockIdx.z batches via element offsets.
// ---------------------------------------------------------------------------
#define ASTR_B      144
#define PLANE_B     (128 * ASTR_B)          // 18432
#define STAGE_B     (2 * PLANE_B)           // 36864
#define NSTAGE      3
#define GEMM_SMEM   (NSTAGE * STAGE_B)      // 110592

__device__ __forceinline__ void ld_plane(
    const __half* __restrict__ gsrc, int row0, int lda, int k0, char* stp, int tid)
{
#pragma unroll
    for (int j = 0; j < 4; j++) {
        int cid = j * 256 + tid;
        int r = cid >> 3;
        int c = cid & 7;
        const void* src = gsrc + (size_t)(row0 + r) * lda + k0 + c * 8;
        uint32_t dst = smem_to_u32(stp + r * ASTR_B + c * 16);
        CP_ASYNC16(dst, src);
    }
}

__global__ __launch_bounds__(256, 2) void hmma_gemm(
    const __half* __restrict__ Ahi, const __half* __restrict__ Bhi,
    float* __restrict__ C, int lda, int K, int Nc,
    size_t batchA, size_t batchB, size_t batchC)
{
    extern __shared__ char smem[];
    const int tid  = threadIdx.x;
    const int lane = tid & 31;
    const int warp = tid >> 5;
    const int wm   = warp & 1;
    const int wn   = warp >> 1;
    const int g    = lane >> 2;
    const int tg   = lane & 3;
    const int rowA = blockIdx.y * 128;
    const int rowB = blockIdx.x * 128;

    const __half* Ah = Ahi + blockIdx.z * batchA;
    const __half* Bh = Bhi + blockIdx.z * batchB;
    float* Cz = C + blockIdx.z * batchC;

    float acc[4][4][4];
#pragma unroll
    for (int i = 0; i < 4; i++)
#pragma unroll
        for (int j = 0; j < 4; j++)
#pragma unroll
            for (int r = 0; r < 4; r++) acc[i][j][r] = 0.f;

    const int a_r = lane & 15;
    const int a_c = (lane >> 4) * 16;
    const int b_r = (lane & 7) + (((lane >> 4) & 1) << 3);
    const int b_c = ((lane >> 3) & 1) * 16;

    const int T = K >> 6;          // K multiple of 64 at all call sites

    // prologue: stages 0,1
#pragma unroll
    for (int s = 0; s < 2; s++) {
        char* st = smem + s * STAGE_B;
        ld_plane(Ah, rowA, lda, s * 64, st + 0,       tid);
        ld_plane(Bh, rowB, K,   s * 64, st + PLANE_B, tid);
        CP_COMMIT();
    }

    int slot = 0;
    for (int t = 0; t < T; t++) {
        if (t + 1 < T) { CP_WAIT(1); } else { CP_WAIT(0); }
        __syncthreads();

        if (t + 2 < T) {
            int ns = slot - 1; if (ns < 0) ns += NSTAGE;   // (slot+2)%3
            char* st = smem + ns * STAGE_B;
            const int k0 = (t + 2) << 6;
            ld_plane(Ah, rowA, lda, k0, st + 0,       tid);
            ld_plane(Bh, rowB, K,   k0, st + PLANE_B, tid);
            CP_COMMIT();
        }

        char* st = smem + slot * STAGE_B;
        const uint32_t aB = smem_to_u32(st) + (wm * 64) * ASTR_B;
        const uint32_t bB = smem_to_u32(st) + PLANE_B + (wn * 32) * ASTR_B;

#pragma unroll
        for (int s = 0; s < 4; s++) {
            const int koff = s * 32;
            uint32_t ahi[4][4];
#pragma unroll
            for (int mt = 0; mt < 4; mt++) {
                uint32_t addr = aB + (mt * 16 + a_r) * ASTR_B + a_c + koff;
                LDSM_X4(ahi[mt], addr);
            }
#pragma unroll
            for (int np = 0; np < 2; np++) {
                uint32_t baddr = bB + (np * 16 + b_r) * ASTR_B + b_c + koff;
                uint32_t bh[4];
                LDSM_X4(bh, baddr);
#pragma unroll
                for (int mt = 0; mt < 4; mt++) {
                    mma16816(acc[mt][np * 2 + 0], ahi[mt], bh + 0);
                    mma16816(acc[mt][np * 2 + 1], ahi[mt], bh + 2);
                }
            }
        }
        slot++; if (slot == NSTAGE) slot = 0;
    }

#pragma unroll
    for (int mt = 0; mt < 4; mt++) {
#pragma unroll
        for (int half = 0; half < 2; half++) {
            int gr = blockIdx.y * 128 + wm * 64 + mt * 16 + g + half * 8;
            float* crow = Cz + (size_t)gr * Nc;
#pragma unroll
            for (int nt = 0; nt < 4; nt++) {
                int gc = blockIdx.x * 128 + wn * 32 + nt * 8 + tg * 2;
                if (gc + 1 < Nc) {
                    crow[gc]     = acc[mt][nt][half * 2 + 0];
                    crow[gc + 1] = acc[mt][nt][half * 2 + 1];
                }
            }
        }
    }
}

// ---------------------------------------------------------------------------
// prep kernels
// ---------------------------------------------------------------------------
__global__ __launch_bounds__(256) void convert_rows_kernel(
    const float* __restrict__ in, __half* __restrict__ hi, size_t n4)
{
    size_t i = (size_t)blockIdx.x * blockDim.x + threadIdx.x;
    if (i >= n4) return;
    float4 v = ((const float4*)in)[i];
    ((__half2*)hi)[i * 2 + 0] = __halves2half2(__float2half(v.x), __float2half(v.y));
    ((__half2*)hi)[i * 2 + 1] = __halves2half2(__float2half(v.z), __float2half(v.w));
}

__global__ void transpose_h_kernel(
    const float* __restrict__ W, __half* __restrict__ bh, int Ktot, int koff, int Nv)
{
    __shared__ float t[32][33];
    const int n0 = blockIdx.x * 32, k0 = blockIdx.y * 32;
    const int tx = threadIdx.x, ty = threadIdx.y;
#pragma unroll
    for (int i = 0; i < 32; i += 8) {
        int n = n0 + tx;
        t[ty + i][tx] = (n < Nv) ? W[(size_t)(k0 + ty + i) * Nv + n] : 0.f;
    }
    __syncthreads();
#pragma unroll
    for (int i = 0; i < 32; i += 8) {
        int n = n0 + ty + i, k = k0 + tx;
        bh[(size_t)n * Ktot + koff + k] = __float2half(t[tx][ty + i]);
    }
}

// ---------------------------------------------------------------------------
// Depthwise conv1d (D_CONV=4) + SiLU, both directions; fp16 output only.
// ---------------------------------------------------------------------------
__global__ __launch_bounds__(256) void conv_silu_kernel(
    const float* __restrict__ cwf, const float* __restrict__ cbf,
    const float* __restrict__ cwb, const float* __restrict__ cbb)
{
    size_t idx = (size_t)blockIdx.x * blockDim.x + threadIdx.x;
    if (idx >= (size_t)M_ROWS * FOUR_E) return;
    const int c = (int)(idx & (FOUR_E - 1));
    const int m = (int)(idx >> 12);
    const int dir = c >> 11;
    const int e = c & (E_DIM - 1);
    const int l = m & (L_SEQ - 1);

    const float* cw = dir ? cwb : cwf;
    const float* cb = dir ? cbb : cbf;
    const float* src = g_xz + (size_t)m * EIGHT_E + dir * 4096 + e;

    float acc = cb[e];
#pragma unroll
    for (int t = 0; t < 4; t++) {
        int off  = dir ? t : t - 3;
        int widx = dir ? 3 - t : t;
        int ll = l + off;
        if (ll >= 0 && ll < L_SEQ)
            acc = fmaf(src[(ptrdiff_t)off * EIGHT_E], cw[e * 4 + widx], acc);
    }
    float v = acc / (1.f + __expf(-acc));
    g_xihi[idx] = __float2half(v);
}

// ---------------------------------------------------------------------------
// delta = softplus( proj[:, :64] @ dt_w + dt_b );  16 m-rows per block.
// (FFMA pipe - a K=64 tensor-core GEMM is latency-bound: R13 post-mortem.)
// ---------------------------------------------------------------------------
__device__ __forceinline__ float softplusf(float x)
{
    return (x > 20.f) ? x : log1pf(__expf(x));
}

__global__ __launch_bounds__(256) void delta_kernel(
    const float* __restrict__ dtw_f, const float* __restrict__ dtb_f,
    const float* __restrict__ dtw_b, const float* __restrict__ dtb_b)
{
    __shared__ float s[16][DT_RANK];
    const int dir = blockIdx.z;
    const float* dtw = dir ? dtw_b : dtw_f;
    const float* dtb = dir ? dtb_b : dtb_f;
    const int m0 = blockIdx.y * 16;
    const int col = blockIdx.x * 1024 + threadIdx.x * 4;

    const float* pbase = g_proj + (size_t)dir * M_ROWS * PROJ_N;
#pragma unroll
    for (int i = threadIdx.x; i < 16 * DT_RANK; i += 256) {
        int row = i >> 6, r = i & 63;
        s[row][r] = pbase[(size_t)(m0 + row) * PROJ_N + r];
    }
    __syncthreads();

    float4 bias = *(const float4*)(dtb + col);
    float4 acc[16];
#pragma unroll
    for (int row = 0; row < 16; row++) acc[row] = bias;

#pragma unroll 2
    for (int r = 0; r < DT_RANK; r++) {
        float4 w = *(const float4*)(dtw + (size_t)r * E_DIM + col);
#pragma unroll
        for (int row = 0; row < 16; row++) {
            float sv = s[row][r];
            acc[row].x = fmaf(sv, w.x, acc[row].x);
            acc[row].y = fmaf(sv, w.y, acc[row].y);
            acc[row].z = fmaf(sv, w.z, acc[row].z);
            acc[row].w = fmaf(sv, w.w, acc[row].w);
        }
    }
#pragma unroll
    for (int row = 0; row < 16; row++) {
        float4 o;
        o.x = softplusf(acc[row].x);
        o.y = softplusf(acc[row].y);
        o.z = softplusf(acc[row].z);
        o.w = softplusf(acc[row].w);
        *(float4*)(g_delta + (size_t)(m0 + row) * FOUR_E + dir * E_DIM + col) = o;
    }
}

// ---------------------------------------------------------------------------
// Selective scan + fused output gating: 4 lanes/chain, 8 chains/warp.
// u read from fp16 plane.  Fast path: A[e,n]=(n+1)*A[e,0] -> power ladder.
// ---------------------------------------------------------------------------
__global__ __launch_bounds__(256) void scan_kernel(
    const float* __restrict__ Alog_f, const float* __restrict__ Alog_b,
    const float* __restrict__ Dp_f,  const float* __restrict__ Dp_b)
{
    const int lane = threadIdx.x & 31;
    const int wglob = blockIdx.x * 8 + (threadIdx.x >> 5);
    const int t = lane & 3;
    const int chain = wglob * 8 + (lane >> 2);
    const int dir = chain >> 13;
    const int b = (chain >> 11) & 3;
    const int e = chain & (E_DIM - 1);
    const int col = dir * E_DIM + e;
    const int n0 = t * 4;

    const float* Al = dir ? Alog_b : Alog_f;
    const float Dpe = (dir ? Dp_b : Dp_f)[e];
    float a[4];
#pragma unroll
    for (int j = 0; j < 4; j++) a[j] = -__expf(Al[e * N_ST + n0 + j]);
    const float a0 = __shfl_sync(0xffffffffu, a[0], lane & ~3);

    bool ok = true;
#pragma unroll
    for (int j = 0; j < 4; j++) {
        float expect = (float)(n0 + j + 1) * a0;
        ok = ok && (fabsf(a[j] - expect) <= 1e-5f * fmaxf(fabsf(a[j]), 1e-20f));
    }
    const bool fast = __all_sync(0xffffffffu, ok);

    const int l0 = dir ? (L_SEQ - 1) : 0;
    const ptrdiff_t strideE = dir ? -FOUR_E : FOUR_E;
    const ptrdiff_t strideZ = dir ? -EIGHT_E : EIGHT_E;
    const ptrdiff_t strideP = dir ? -PROJ_N : PROJ_N;

    const float*  dp = g_delta + (size_t)(b * L_SEQ + l0) * FOUR_E + col;
    const __half* up = g_xihi  + (size_t)(b * L_SEQ + l0) * FOUR_E + col;
    const float*  zp = g_xz    + (size_t)(b * L_SEQ + l0) * EIGHT_E + dir * 4096 + 2048 + e;
    const float*  pp = g_proj  + (size_t)dir * M_ROWS * PROJ_N
                              + (size_t)(b * L_SEQ + l0) * PROJ_N;
    __half*       yp = g_yhi   + (size_t)(b * L_SEQ + l0) * FOUR_E + col;

    float h0 = 0.f, h1 = 0.f, h2 = 0.f, h3 = 0.f;
    float d = dp[0];
    float u = __half2float(up[0]);
    float zv = zp[0];
    float4 Bv = *(const float4*)(pp + 64 + n0);
    float4 Cv = *(const float4*)(pp + 80 + n0);

    for (int i = 0; i < L_SEQ; i++) {
        float dn = 0.f, un = 0.f, zn = 0.f;
        float4 Bn = make_float4(0.f, 0.f, 0.f, 0.f);
        float4 Cn = Bn;
        if (i + 1 < L_SEQ) {
            dn = dp[strideE];
            un = __half2float(up[strideE]);
            zn = zp[strideZ];
            Bn = *(const float4*)(pp + strideP + 64 + n0);
            Cn = *(const float4*)(pp + strideP + 80 + n0);
        }

        float d0, d1, d2, d3;
        if (fast) {
            float pb = __expf(d * a0);
            float p2 = pb * pb;
            float p4 = p2 * p2;
            float p8 = p4 * p4;
            float sel = (t == 0) ? 1.f : (t == 1) ? p4 : (t == 2) ? p8 : p8 * p4;
            d0 = sel * pb;
            d1 = d0 * pb;
            d2 = d1 * pb;
            d3 = d2 * pb;
        } else {
            d0 = __expf(d * a[0]);
            d1 = __expf(d * a[1]);
            d2 = __expf(d * a[2]);
            d3 = __expf(d * a[3]);
        }

        const float du = d * u;
        h0 = fmaf(d0, h0, du * Bv.x);
        h1 = fmaf(d1, h1, du * Bv.y);
        h2 = fmaf(d2, h2, du * Bv.z);
        h3 = fmaf(d3, h3, du * Bv.w);

        float v = h0 * Cv.x;
        v = fmaf(h1, Cv.y, v);
        v = fmaf(h2, Cv.z, v);
        v = fmaf(h3, Cv.w, v);
        v += __shfl_xor_sync(0xffffffffu, v, 1);
        v += __shfl_xor_sync(0xffffffffu, v, 2);
        if (t == 0) {
            float sz = zv / (1.f + __expf(-zv));
            *yp = __float2half((v + u * Dpe) * sz);
        }

        dp += strideE; up += strideE; zp += strideZ; yp += strideE; pp += strideP;
        d = dn; u = un; zv = zn; Bv = Bn; Cv = Cn;
    }
}

// ---------------------------------------------------------------------------
// Launcher
// ---------------------------------------------------------------------------
extern "C" void kernel_launch(void* const* d_in, const int* in_sizes, int n_in,
                              void* d_out, int out_size)
{
    (void)in_sizes; (void)n_in; (void)out_size;
    const float* x = (const float*)d_in[0];
    float* out = (float*)d_out;

    cudaFuncSetAttribute(hmma_gemm, cudaFuncAttributeMaxDynamicSharedMemorySize, GEMM_SMEM);

    const float* P[2][9];
    for (int dir = 0; dir < 2; dir++)
        for (int j = 0; j < 9; j++)
            P[dir][j] = (const float*)d_in[1 + dir * 9 + j];

    __half *xhi, *xihi, *yhi, *btin, *btxp, *btout;
    float *p_xz, *p_proj;
    cudaGetSymbolAddress((void**)&xhi, g_xhi);
    cudaGetSymbolAddress((void**)&xihi, g_xihi);
    cudaGetSymbolAddress((void**)&yhi, g_yhi);
    cudaGetSymbolAddress((void**)&btin, g_btin);
    cudaGetSymbolAddress((void**)&btxp, g_btxp);
    cudaGetSymbolAddress((void**)&btout, g_btout);
    cudaGetSymbolAddress((void**)&p_xz, g_xz);
    cudaGetSymbolAddress((void**)&p_proj, g_proj);

    // ---- weight prep ----
    transpose_h_kernel<<<dim3(128, 32), dim3(32, 8)>>>(P[0][0], btin, D_MODEL, 0, 4096);
    transpose_h_kernel<<<dim3(128, 32), dim3(32, 8)>>>(
        P[1][0], btin + (size_t)4096 * D_MODEL, D_MODEL, 0, 4096);
    for (int dir = 0; dir < 2; dir++)
        transpose_h_kernel<<<dim3(4, 64), dim3(32, 8)>>>(
            P[dir][3], btxp + (size_t)dir * 128 * E_DIM, E_DIM, 0, PROJ_N);
    transpose_h_kernel<<<dim3(32, 64), dim3(32, 8)>>>(P[0][8], btout, FOUR_E, 0, D_MODEL);
    transpose_h_kernel<<<dim3(32, 64), dim3(32, 8)>>>(P[1][8], btout, FOUR_E, 2048, D_MODEL);

    // ---- convert x to fp16 ----
    {
        size_t n4 = (size_t)M_ROWS * D_MODEL / 4;
        convert_rows_kernel<<<(unsigned)((n4 + 255) / 256), 256>>>(x, xhi, n4);
    }

    // 1) xz = x @ [in_w_f | in_w_b]
    hmma_gemm<<<dim3(EIGHT_E / 128, M_ROWS / 128, 1), 256, GEMM_SMEM>>>(
        xhi, btin, p_xz, D_MODEL, D_MODEL, EIGHT_E, 0, 0, 0);

    // 2) conv + silu, both dirs (fp16 output only)
    {
        size_t n = (size_t)M_ROWS * FOUR_E;
        conv_silu_kernel<<<(unsigned)((n + 255) / 256), 256>>>(
            P[0][1], P[0][2], P[1][1], P[1][2]);
    }

    // 3) proj: both dirs batched via blockIdx.z
    hmma_gemm<<<dim3(1, M_ROWS / 128, 2), 256, GEMM_SMEM>>>(
        xihi, btxp, p_proj, FOUR_E, E_DIM, PROJ_N,
        (size_t)E_DIM, (size_t)128 * E_DIM, (size_t)M_ROWS * PROJ_N);

    // 4) delta (both dirs, FFMA)
    delta_kernel<<<dim3(2, M_ROWS / 16, 2), 256>>>(P[0][4], P[0][5], P[1][4], P[1][5]);

    // 5) selective scan + fused gating (both dirs)
    scan_kernel<<<256, 256>>>(P[0][6], P[1][6], P[0][7], P[1][7]);

    // 6) out = [y_f | y_b] @ [out_w_f ; out_w_b]
    hmma_gemm<<<dim3(D_MODEL / 128, M_ROWS / 128, 1), 256, GEMM_SMEM>>>(
        yhi, btout, out, FOUR_E, FOUR_E, D_MODEL, 0, 0, 0);
}

// round 16
// speedup vs baseline: 1.1916x; 1.1916x over previous
#include <cuda_runtime.h>
#include <cuda_fp16.h>
#include <math.h>
#include <stdint.h>

// ---------------------------------------------------------------------------
// BidirectionalMamba: D=1024, E=2048, N=16, dt_rank=64, B=4, L=2048.
// fwd: causal conv + forward scan.  bwd: anti-causal conv + backward scan.
// R12 configuration (best measured): 1-term fp16 GEMMs (fp32 accum, BK=64),
// conv emits fp32 + fp16 xi, scan reads fp32 u (fp16-u measured regression),
// FFMA delta, scan fuses output gating.  New: smem-tiled conv (3.7x fewer
// global reads, bit-identical math).
// ---------------------------------------------------------------------------
#define D_MODEL  1024
#define E_DIM    2048
#define FOUR_E   4096
#define EIGHT_E  8192
#define N_ST     16
#define DT_RANK  64
#define PROJ_N   96
#define B_SZ     4
#define L_SEQ    2048
#define M_ROWS   8192

__device__ float g_xz[(size_t)M_ROWS * EIGHT_E];
__device__ float g_xi[(size_t)M_ROWS * FOUR_E];
__device__ float g_delta[(size_t)M_ROWS * FOUR_E];
__device__ float g_proj[(size_t)2 * M_ROWS * PROJ_N];

__device__ __half g_xhi[(size_t)M_ROWS * D_MODEL];
__device__ __half g_xihi[(size_t)M_ROWS * FOUR_E];
__device__ __half g_yhi[(size_t)M_ROWS * FOUR_E];
__device__ __half g_btin[(size_t)EIGHT_E * D_MODEL];
__device__ __half g_btxp[(size_t)2 * 128 * E_DIM];
__device__ __half g_btout[(size_t)D_MODEL * FOUR_E];

// ---------------------------------------------------------------------------
// helpers
// ---------------------------------------------------------------------------
__device__ __forceinline__ uint32_t smem_to_u32(const void* p)
{
    uint32_t a;
    asm("{ .reg .u64 t; cvta.to.shared.u64 t, %1; cvt.u32.u64 %0, t; }" : "=r"(a) : "l"(p));
    return a;
}

#define LDSM_X4(r, a) \
    asm volatile("ldmatrix.sync.aligned.m8n8.x4.shared.b16 {%0,%1,%2,%3}, [%4];" \
        : "=r"((r)[0]), "=r"((r)[1]), "=r"((r)[2]), "=r"((r)[3]) : "r"(a))

__device__ __forceinline__ void mma16816(float* d, const uint32_t* a, const uint32_t* b)
{
    asm volatile(
        "mma.sync.aligned.m16n8k16.row.col.f32.f16.f16.f32 "
        "{%0,%1,%2,%3}, {%4,%5,%6,%7}, {%8,%9}, {%0,%1,%2,%3};"
        : "+f"(d[0]), "+f"(d[1]), "+f"(d[2]), "+f"(d[3])
        : "r"(a[0]), "r"(a[1]), "r"(a[2]), "r"(a[3]), "r"(b[0]), "r"(b[1]));
}

#define CP_ASYNC16(dst, src) \
    asm volatile("cp.async.cg.shared.global [%0], [%1], 16;" :: "r"(dst), "l"(src))
#define CP_COMMIT()  asm volatile("cp.async.commit_group;" ::: "memory")
#define CP_WAIT(n)   asm volatile("cp.async.wait_group %0;" :: "n"(n) : "memory")

// ---------------------------------------------------------------------------
// fp16 HMMA GEMM: C[M,N] = A[M,K] @ W[K,N]  (B = W^T, fp16).
// 128x128 tile, BK=64, 8 warps (2x4), warp 64x32, 3-stage cp.async ring,
// one barrier per k-tile, loads into slot+2.  Row pitch 144B keeps LDSM
// conflict-free.  2 CTAs/SM.  blockIdx.z batches via element offsets.
// ---------------------------------------------------------------------------
#define ASTR_B      144
#define PLANE_B     (128 * ASTR_B)          // 18432
#define STAGE_B     (2 * PLANE_B)           // 36864
#define NSTAGE      3
#define GEMM_SMEM   (NSTAGE * STAGE_B)      // 110592

__device__ __forceinline__ void ld_plane(
    const __half* __restrict__ gsrc, int row0, int lda, int k0, char* stp, int tid)
{
#pragma unroll
    for (int j = 0; j < 4; j++) {
        int cid = j * 256 + tid;
        int r = cid >> 3;
        int c = cid & 7;
        const void* src = gsrc + (size_t)(row0 + r) * lda + k0 + c * 8;
        uint32_t dst = smem_to_u32(stp + r * ASTR_B + c * 16);
        CP_ASYNC16(dst, src);
    }
}

__global__ __launch_bounds__(256, 2) void hmma_gemm(
    const __half* __restrict__ Ahi, const __half* __restrict__ Bhi,
    float* __restrict__ C, int lda, int K, int Nc,
    size_t batchA, size_t batchB, size_t batchC)
{
    extern __shared__ char smem[];
    const int tid  = threadIdx.x;
    const int lane = tid & 31;
    const int warp = tid >> 5;
    const int wm   = warp & 1;
    const int wn   = warp >> 1;
    const int g    = lane >> 2;
    const int tg   = lane & 3;
    const int rowA = blockIdx.y * 128;
    const int rowB = blockIdx.x * 128;

    const __half* Ah = Ahi + blockIdx.z * batchA;
    const __half* Bh = Bhi + blockIdx.z * batchB;
    float* Cz = C + blockIdx.z * batchC;

    float acc[4][4][4];
#pragma unroll
    for (int i = 0; i < 4; i++)
#pragma unroll
        for (int j = 0; j < 4; j++)
#pragma unroll
            for (int r = 0; r < 4; r++) acc[i][j][r] = 0.f;

    const int a_r = lane & 15;
    const int a_c = (lane >> 4) * 16;
    const int b_r = (lane & 7) + (((lane >> 4) & 1) << 3);
    const int b_c = ((lane >> 3) & 1) * 16;

    const int T = K >> 6;          // K multiple of 64 at all call sites

    // prologue: stages 0,1
#pragma unroll
    for (int s = 0; s < 2; s++) {
        char* st = smem + s * STAGE_B;
        ld_plane(Ah, rowA, lda, s * 64, st + 0,       tid);
        ld_plane(Bh, rowB, K,   s * 64, st + PLANE_B, tid);
        CP_COMMIT();
    }

    int slot = 0;
    for (int t = 0; t < T; t++) {
        if (t + 1 < T) { CP_WAIT(1); } else { CP_WAIT(0); }
        __syncthreads();

        if (t + 2 < T) {
            int ns = slot - 1; if (ns < 0) ns += NSTAGE;   // (slot+2)%3
            char* st = smem + ns * STAGE_B;
            const int k0 = (t + 2) << 6;
            ld_plane(Ah, rowA, lda, k0, st + 0,       tid);
            ld_plane(Bh, rowB, K,   k0, st + PLANE_B, tid);
            CP_COMMIT();
        }

        char* st = smem + slot * STAGE_B;
        const uint32_t aB = smem_to_u32(st) + (wm * 64) * ASTR_B;
        const uint32_t bB = smem_to_u32(st) + PLANE_B + (wn * 32) * ASTR_B;

#pragma unroll
        for (int s = 0; s < 4; s++) {
            const int koff = s * 32;
            uint32_t ahi[4][4];
#pragma unroll
            for (int mt = 0; mt < 4; mt++) {
                uint32_t addr = aB + (mt * 16 + a_r) * ASTR_B + a_c + koff;
                LDSM_X4(ahi[mt], addr);
            }
#pragma unroll
            for (int np = 0; np < 2; np++) {
                uint32_t baddr = bB + (np * 16 + b_r) * ASTR_B + b_c + koff;
                uint32_t bh[4];
                LDSM_X4(bh, baddr);
#pragma unroll
                for (int mt = 0; mt < 4; mt++) {
                    mma16816(acc[mt][np * 2 + 0], ahi[mt], bh + 0);
                    mma16816(acc[mt][np * 2 + 1], ahi[mt], bh + 2);
                }
            }
        }
        slot++; if (slot == NSTAGE) slot = 0;
    }

#pragma unroll
    for (int mt = 0; mt < 4; mt++) {
#pragma unroll
        for (int half = 0; half < 2; half++) {
            int gr = blockIdx.y * 128 + wm * 64 + mt * 16 + g + half * 8;
            float* crow = Cz + (size_t)gr * Nc;
#pragma unroll
            for (int nt = 0; nt < 4; nt++) {
                int gc = blockIdx.x * 128 + wn * 32 + nt * 8 + tg * 2;
                if (gc + 1 < Nc) {
                    crow[gc]     = acc[mt][nt][half * 2 + 0];
                    crow[gc + 1] = acc[mt][nt][half * 2 + 1];
                }
            }
        }
    }
}

// ---------------------------------------------------------------------------
// prep kernels
// ---------------------------------------------------------------------------
__global__ __launch_bounds__(256) void convert_rows_kernel(
    const float* __restrict__ in, __half* __restrict__ hi, size_t n4)
{
    size_t i = (size_t)blockIdx.x * blockDim.x + threadIdx.x;
    if (i >= n4) return;
    float4 v = ((const float4*)in)[i];
    ((__half2*)hi)[i * 2 + 0] = __halves2half2(__float2half(v.x), __float2half(v.y));
    ((__half2*)hi)[i * 2 + 1] = __halves2half2(__float2half(v.z), __float2half(v.w));
}

__global__ void transpose_h_kernel(
    const float* __restrict__ W, __half* __restrict__ bh, int Ktot, int koff, int Nv)
{
    __shared__ float t[32][33];
    const int n0 = blockIdx.x * 32, k0 = blockIdx.y * 32;
    const int tx = threadIdx.x, ty = threadIdx.y;
#pragma unroll
    for (int i = 0; i < 32; i += 8) {
        int n = n0 + tx;
        t[ty + i][tx] = (n < Nv) ? W[(size_t)(k0 + ty + i) * Nv + n] : 0.f;
    }
    __syncthreads();
#pragma unroll
    for (int i = 0; i < 32; i += 8) {
        int n = n0 + ty + i, k = k0 + tx;
        bh[(size_t)n * Ktot + koff + k] = __float2half(t[tx][ty + i]);
    }
}

// ---------------------------------------------------------------------------
// Depthwise conv1d (D_CONV=4) + SiLU, smem-tiled: block = 32 l x 64 e for one
// (b, dir).  Halo of 3 rows; out-of-range rows zeroed (fma with 0 = exact).
// Emits fp32 g_xi and fp16 g_xihi (identical numerics to untiled version).
// ---------------------------------------------------------------------------
__global__ __launch_bounds__(256) void conv_silu_kernel(
    const float* __restrict__ cwf, const float* __restrict__ cbf,
    const float* __restrict__ cwb, const float* __restrict__ cbb)
{
    __shared__ float s[35][64];

    const int dir = blockIdx.x >> 5;
    const int e0  = (blockIdx.x & 31) * 64;
    const int l0  = blockIdx.y * 32;
    const int b   = blockIdx.z;
    const int tid = threadIdx.x;

    const float* cw = dir ? cwb : cwf;
    const float* cb = dir ? cbb : cbf;

    // load rows: fwd l = l0 + r - 3, bwd l = l0 + r   (r = 0..34)
    const int lbase = dir ? l0 : (l0 - 3);
    for (int i = tid; i < 35 * 64; i += 256) {
        int r = i >> 6;
        int c = i & 63;
        int l = lbase + r;
        float v = 0.f;
        if (l >= 0 && l < L_SEQ)
            v = g_xz[(size_t)(b * L_SEQ + l) * EIGHT_E + dir * 4096 + e0 + c];
        s[r][c] = v;
    }
    __syncthreads();

    const int c  = tid & 63;
    const int r0 = (tid >> 6) * 8;
    const int e  = e0 + c;

    // weight order: fwd w[0..3], bwd w[3..0]
    float w0 = cw[e * 4 + (dir ? 3 : 0)];
    float w1 = cw[e * 4 + (dir ? 2 : 1)];
    float w2 = cw[e * 4 + (dir ? 1 : 2)];
    float w3 = cw[e * 4 + (dir ? 0 : 3)];
    const float bias = cb[e];

#pragma unroll
    for (int j = 0; j < 8; j++) {
        const int lr = r0 + j;
        float acc = bias;
        acc = fmaf(s[lr + 0][c], w0, acc);
        acc = fmaf(s[lr + 1][c], w1, acc);
        acc = fmaf(s[lr + 2][c], w2, acc);
        acc = fmaf(s[lr + 3][c], w3, acc);
        float v = acc / (1.f + __expf(-acc));
        size_t idx = (size_t)(b * L_SEQ + l0 + lr) * FOUR_E + dir * E_DIM + e;
        g_xi[idx] = v;
        g_xihi[idx] = __float2half(v);
    }
}

// ---------------------------------------------------------------------------
// delta = softplus( proj[:, :64] @ dt_w + dt_b );  16 m-rows per block (FFMA).
// ---------------------------------------------------------------------------
__device__ __forceinline__ float softplusf(float x)
{
    return (x > 20.f) ? x : log1pf(__expf(x));
}

__global__ __launch_bounds__(256) void delta_kernel(
    const float* __restrict__ dtw_f, const float* __restrict__ dtb_f,
    const float* __restrict__ dtw_b, const float* __restrict__ dtb_b)
{
    __shared__ float s[16][DT_RANK];
    const int dir = blockIdx.z;
    const float* dtw = dir ? dtw_b : dtw_f;
    const float* dtb = dir ? dtb_b : dtb_f;
    const int m0 = blockIdx.y * 16;
    const int col = blockIdx.x * 1024 + threadIdx.x * 4;

    const float* pbase = g_proj + (size_t)dir * M_ROWS * PROJ_N;
#pragma unroll
    for (int i = threadIdx.x; i < 16 * DT_RANK; i += 256) {
        int row = i >> 6, r = i & 63;
        s[row][r] = pbase[(size_t)(m0 + row) * PROJ_N + r];
    }
    __syncthreads();

    float4 bias = *(const float4*)(dtb + col);
    float4 acc[16];
#pragma unroll
    for (int row = 0; row < 16; row++) acc[row] = bias;

#pragma unroll 2
    for (int r = 0; r < DT_RANK; r++) {
        float4 w = *(const float4*)(dtw + (size_t)r * E_DIM + col);
#pragma unroll
        for (int row = 0; row < 16; row++) {
            float sv = s[row][r];
            acc[row].x = fmaf(sv, w.x, acc[row].x);
            acc[row].y = fmaf(sv, w.y, acc[row].y);
            acc[row].z = fmaf(sv, w.z, acc[row].z);
            acc[row].w = fmaf(sv, w.w, acc[row].w);
        }
    }
#pragma unroll
    for (int row = 0; row < 16; row++) {
        float4 o;
        o.x = softplusf(acc[row].x);
        o.y = softplusf(acc[row].y);
        o.z = softplusf(acc[row].z);
        o.w = softplusf(acc[row].w);
        *(float4*)(g_delta + (size_t)(m0 + row) * FOUR_E + dir * E_DIM + col) = o;
    }
}

// ---------------------------------------------------------------------------
// Selective scan + fused output gating: 4 lanes/chain, 8 chains/warp.
// fp32 u (fp16-u path measured as a regression in R13/R14).
// Fast path (verified): A[e,n] = (n+1)*A[e,0]  ->  decay_n = pb^(n+1).
// ---------------------------------------------------------------------------
__global__ __launch_bounds__(256) void scan_kernel(
    const float* __restrict__ Alog_f, const float* __restrict__ Alog_b,
    const float* __restrict__ Dp_f,  const float* __restrict__ Dp_b)
{
    const int lane = threadIdx.x & 31;
    const int wglob = blockIdx.x * 8 + (threadIdx.x >> 5);
    const int t = lane & 3;
    const int chain = wglob * 8 + (lane >> 2);
    const int dir = chain >> 13;
    const int b = (chain >> 11) & 3;
    const int e = chain & (E_DIM - 1);
    const int col = dir * E_DIM + e;
    const int n0 = t * 4;

    const float* Al = dir ? Alog_b : Alog_f;
    const float Dpe = (dir ? Dp_b : Dp_f)[e];
    float a[4];
#pragma unroll
    for (int j = 0; j < 4; j++) a[j] = -__expf(Al[e * N_ST + n0 + j]);
    const float a0 = __shfl_sync(0xffffffffu, a[0], lane & ~3);

    bool ok = true;
#pragma unroll
    for (int j = 0; j < 4; j++) {
        float expect = (float)(n0 + j + 1) * a0;
        ok = ok && (fabsf(a[j] - expect) <= 1e-5f * fmaxf(fabsf(a[j]), 1e-20f));
    }
    const bool fast = __all_sync(0xffffffffu, ok);

    const int l0 = dir ? (L_SEQ - 1) : 0;
    const ptrdiff_t strideE = dir ? -FOUR_E : FOUR_E;
    const ptrdiff_t strideZ = dir ? -EIGHT_E : EIGHT_E;
    const ptrdiff_t strideP = dir ? -PROJ_N : PROJ_N;

    const float* dp = g_delta + (size_t)(b * L_SEQ + l0) * FOUR_E + col;
    const float* up = g_xi    + (size_t)(b * L_SEQ + l0) * FOUR_E + col;
    const float* zp = g_xz    + (size_t)(b * L_SEQ + l0) * EIGHT_E + dir * 4096 + 2048 + e;
    const float* pp = g_proj  + (size_t)dir * M_ROWS * PROJ_N
                             + (size_t)(b * L_SEQ + l0) * PROJ_N;
    __half*      yp = g_yhi   + (size_t)(b * L_SEQ + l0) * FOUR_E + col;

    float h0 = 0.f, h1 = 0.f, h2 = 0.f, h3 = 0.f;
    float d = dp[0];
    float u = up[0];
    float zv = zp[0];
    float4 Bv = *(const float4*)(pp + 64 + n0);
    float4 Cv = *(const float4*)(pp + 80 + n0);

    for (int i = 0; i < L_SEQ; i++) {
        float dn = 0.f, un = 0.f, zn = 0.f;
        float4 Bn = make_float4(0.f, 0.f, 0.f, 0.f);
        float4 Cn = Bn;
        if (i + 1 < L_SEQ) {
            dn = dp[strideE];
            un = up[strideE];
            zn = zp[strideZ];
            Bn = *(const float4*)(pp + strideP + 64 + n0);
            Cn = *(const float4*)(pp + strideP + 80 + n0);
        }

        float d0, d1, d2, d3;
        if (fast) {
            float pb = __expf(d * a0);
            float p2 = pb * pb;
            float p4 = p2 * p2;
            float p8 = p4 * p4;
            float sel = (t == 0) ? 1.f : (t == 1) ? p4 : (t == 2) ? p8 : p8 * p4;
            d0 = sel * pb;
            d1 = d0 * pb;
            d2 = d1 * pb;
            d3 = d2 * pb;
        } else {
            d0 = __expf(d * a[0]);
            d1 = __expf(d * a[1]);
            d2 = __expf(d * a[2]);
            d3 = __expf(d * a[3]);
        }

        const float du = d * u;
        h0 = fmaf(d0, h0, du * Bv.x);
        h1 = fmaf(d1, h1, du * Bv.y);
        h2 = fmaf(d2, h2, du * Bv.z);
        h3 = fmaf(d3, h3, du * Bv.w);

        float v = h0 * Cv.x;
        v = fmaf(h1, Cv.y, v);
        v = fmaf(h2, Cv.z, v);
        v = fmaf(h3, Cv.w, v);
        v += __shfl_xor_sync(0xffffffffu, v, 1);
        v += __shfl_xor_sync(0xffffffffu, v, 2);
        if (t == 0) {
            float sz = zv / (1.f + __expf(-zv));
            *yp = __float2half((v + u * Dpe) * sz);
        }

        dp += strideE; up += strideE; zp += strideZ; yp += strideE; pp += strideP;
        d = dn; u = un; zv = zn; Bv = Bn; Cv = Cn;
    }
}

// ---------------------------------------------------------------------------
// Launcher
// ---------------------------------------------------------------------------
extern "C" void kernel_launch(void* const* d_in, const int* in_sizes, int n_in,
                              void* d_out, int out_size)
{
    (void)in_sizes; (void)n_in; (void)out_size;
    const float* x = (const float*)d_in[0];
    float* out = (float*)d_out;

    cudaFuncSetAttribute(hmma_gemm, cudaFuncAttributeMaxDynamicSharedMemorySize, GEMM_SMEM);

    const float* P[2][9];
    for (int dir = 0; dir < 2; dir++)
        for (int j = 0; j < 9; j++)
            P[dir][j] = (const float*)d_in[1 + dir * 9 + j];

    __half *xhi, *xihi, *yhi, *btin, *btxp, *btout;
    float *p_xz, *p_proj;
    cudaGetSymbolAddress((void**)&xhi, g_xhi);
    cudaGetSymbolAddress((void**)&xihi, g_xihi);
    cudaGetSymbolAddress((void**)&yhi, g_yhi);
    cudaGetSymbolAddress((void**)&btin, g_btin);
    cudaGetSymbolAddress((void**)&btxp, g_btxp);
    cudaGetSymbolAddress((void**)&btout, g_btout);
    cudaGetSymbolAddress((void**)&p_xz, g_xz);
    cudaGetSymbolAddress((void**)&p_proj, g_proj);

    // ---- weight prep ----
    transpose_h_kernel<<<dim3(128, 32), dim3(32, 8)>>>(P[0][0], btin, D_MODEL, 0, 4096);
    transpose_h_kernel<<<dim3(128, 32), dim3(32, 8)>>>(
        P[1][0], btin + (size_t)4096 * D_MODEL, D_MODEL, 0, 4096);
    for (int dir = 0; dir < 2; dir++)
        transpose_h_kernel<<<dim3(4, 64), dim3(32, 8)>>>(
            P[dir][3], btxp + (size_t)dir * 128 * E_DIM, E_DIM, 0, PROJ_N);
    transpose_h_kernel<<<dim3(32, 64), dim3(32, 8)>>>(P[0][8], btout, FOUR_E, 0, D_MODEL);
    transpose_h_kernel<<<dim3(32, 64), dim3(32, 8)>>>(P[1][8], btout, FOUR_E, 2048, D_MODEL);

    // ---- convert x to fp16 ----
    {
        size_t n4 = (size_t)M_ROWS * D_MODEL / 4;
        convert_rows_kernel<<<(unsigned)((n4 + 255) / 256), 256>>>(x, xhi, n4);
    }

    // 1) xz = x @ [in_w_f | in_w_b]
    hmma_gemm<<<dim3(EIGHT_E / 128, M_ROWS / 128, 1), 256, GEMM_SMEM>>>(
        xhi, btin, p_xz, D_MODEL, D_MODEL, EIGHT_E, 0, 0, 0);

    // 2) conv + silu, both dirs (smem-tiled)
    conv_silu_kernel<<<dim3(64, L_SEQ / 32, B_SZ), 256>>>(
        P[0][1], P[0][2], P[1][1], P[1][2]);

    // 3) proj: both dirs batched via blockIdx.z
    hmma_gemm<<<dim3(1, M_ROWS / 128, 2), 256, GEMM_SMEM>>>(
        xihi, btxp, p_proj, FOUR_E, E_DIM, PROJ_N,
        (size_t)E_DIM, (size_t)128 * E_DIM, (size_t)M_ROWS * PROJ_N);

    // 4) delta (both dirs, FFMA)
    delta_kernel<<<dim3(2, M_ROWS / 16, 2), 256>>>(P[0][4], P[0][5], P[1][4], P[1][5]);

    // 5) selective scan + fused gating (both dirs)
    scan_kernel<<<256, 256>>>(P[0][6], P[1][6], P[0][7], P[1][7]);

    // 6) out = [y_f | y_b] @ [out_w_f ; out_w_b]
    hmma_gemm<<<dim3(D_MODEL / 128, M_ROWS / 128, 1), 256, GEMM_SMEM>>>(
        yhi, btout, out, FOUR_E, FOUR_E, D_MODEL, 0, 0, 0);
}

// round 17
// speedup vs baseline: 1.3349x; 1.1203x over previous
#include <cuda_runtime.h>
#include <cuda_fp16.h>
#include <math.h>
#include <stdint.h>

// ---------------------------------------------------------------------------
// BidirectionalMamba: D=1024, E=2048, N=16, dt_rank=64, B=4, L=2048.
// fwd: causal conv + forward scan.  bwd: anti-causal conv + backward scan.
// Config (best measured R15): 1-term fp16 GEMMs (fp32 accum, BK=64),
// smem-tiled conv (fp32+fp16 xi), fp32-u scan, FFMA delta, fused gating.
// New this round: depth-4 software-pipelined loads in the scan.
// ---------------------------------------------------------------------------
#define D_MODEL  1024
#define E_DIM    2048
#define FOUR_E   4096
#define EIGHT_E  8192
#define N_ST     16
#define DT_RANK  64
#define PROJ_N   96
#define B_SZ     4
#define L_SEQ    2048
#define M_ROWS   8192

__device__ float g_xz[(size_t)M_ROWS * EIGHT_E];
__device__ float g_xi[(size_t)M_ROWS * FOUR_E];
__device__ float g_delta[(size_t)M_ROWS * FOUR_E];
__device__ float g_proj[(size_t)2 * M_ROWS * PROJ_N];

__device__ __half g_xhi[(size_t)M_ROWS * D_MODEL];
__device__ __half g_xihi[(size_t)M_ROWS * FOUR_E];
__device__ __half g_yhi[(size_t)M_ROWS * FOUR_E];
__device__ __half g_btin[(size_t)EIGHT_E * D_MODEL];
__device__ __half g_btxp[(size_t)2 * 128 * E_DIM];
__device__ __half g_btout[(size_t)D_MODEL * FOUR_E];

// ---------------------------------------------------------------------------
// helpers
// ---------------------------------------------------------------------------
__device__ __forceinline__ uint32_t smem_to_u32(const void* p)
{
    uint32_t a;
    asm("{ .reg .u64 t; cvta.to.shared.u64 t, %1; cvt.u32.u64 %0, t; }" : "=r"(a) : "l"(p));
    return a;
}

#define LDSM_X4(r, a) \
    asm volatile("ldmatrix.sync.aligned.m8n8.x4.shared.b16 {%0,%1,%2,%3}, [%4];" \
        : "=r"((r)[0]), "=r"((r)[1]), "=r"((r)[2]), "=r"((r)[3]) : "r"(a))

__device__ __forceinline__ void mma16816(float* d, const uint32_t* a, const uint32_t* b)
{
    asm volatile(
        "mma.sync.aligned.m16n8k16.row.col.f32.f16.f16.f32 "
        "{%0,%1,%2,%3}, {%4,%5,%6,%7}, {%8,%9}, {%0,%1,%2,%3};"
        : "+f"(d[0]), "+f"(d[1]), "+f"(d[2]), "+f"(d[3])
        : "r"(a[0]), "r"(a[1]), "r"(a[2]), "r"(a[3]), "r"(b[0]), "r"(b[1]));
}

#define CP_ASYNC16(dst, src) \
    asm volatile("cp.async.cg.shared.global [%0], [%1], 16;" :: "r"(dst), "l"(src))
#define CP_COMMIT()  asm volatile("cp.async.commit_group;" ::: "memory")
#define CP_WAIT(n)   asm volatile("cp.async.wait_group %0;" :: "n"(n) : "memory")

// ---------------------------------------------------------------------------
// fp16 HMMA GEMM: C[M,N] = A[M,K] @ W[K,N]  (B = W^T, fp16).
// 128x128 tile, BK=64, 8 warps (2x4), warp 64x32, 3-stage cp.async ring,
// one barrier per k-tile, loads into slot+2.  Row pitch 144B keeps LDSM
// conflict-free.  2 CTAs/SM.  blockIdx.z batches via element offsets.
// ---------------------------------------------------------------------------
#define ASTR_B      144
#define PLANE_B     (128 * ASTR_B)          // 18432
#define STAGE_B     (2 * PLANE_B)           // 36864
#define NSTAGE      3
#define GEMM_SMEM   (NSTAGE * STAGE_B)      // 110592

__device__ __forceinline__ void ld_plane(
    const __half* __restrict__ gsrc, int row0, int lda, int k0, char* stp, int tid)
{
#pragma unroll
    for (int j = 0; j < 4; j++) {
        int cid = j * 256 + tid;
        int r = cid >> 3;
        int c = cid & 7;
        const void* src = gsrc + (size_t)(row0 + r) * lda + k0 + c * 8;
        uint32_t dst = smem_to_u32(stp + r * ASTR_B + c * 16);
        CP_ASYNC16(dst, src);
    }
}

__global__ __launch_bounds__(256, 2) void hmma_gemm(
    const __half* __restrict__ Ahi, const __half* __restrict__ Bhi,
    float* __restrict__ C, int lda, int K, int Nc,
    size_t batchA, size_t batchB, size_t batchC)
{
    extern __shared__ char smem[];
    const int tid  = threadIdx.x;
    const int lane = tid & 31;
    const int warp = tid >> 5;
    const int wm   = warp & 1;
    const int wn   = warp >> 1;
    const int g    = lane >> 2;
    const int tg   = lane & 3;
    const int rowA = blockIdx.y * 128;
    const int rowB = blockIdx.x * 128;

    const __half* Ah = Ahi + blockIdx.z * batchA;
    const __half* Bh = Bhi + blockIdx.z * batchB;
    float* Cz = C + blockIdx.z * batchC;

    float acc[4][4][4];
#pragma unroll
    for (int i = 0; i < 4; i++)
#pragma unroll
        for (int j = 0; j < 4; j++)
#pragma unroll
            for (int r = 0; r < 4; r++) acc[i][j][r] = 0.f;

    const int a_r = lane & 15;
    const int a_c = (lane >> 4) * 16;
    const int b_r = (lane & 7) + (((lane >> 4) & 1) << 3);
    const int b_c = ((lane >> 3) & 1) * 16;

    const int T = K >> 6;          // K multiple of 64 at all call sites

    // prologue: stages 0,1
#pragma unroll
    for (int s = 0; s < 2; s++) {
        char* st = smem + s * STAGE_B;
        ld_plane(Ah, rowA, lda, s * 64, st + 0,       tid);
        ld_plane(Bh, rowB, K,   s * 64, st + PLANE_B, tid);
        CP_COMMIT();
    }

    int slot = 0;
    for (int t = 0; t < T; t++) {
        if (t + 1 < T) { CP_WAIT(1); } else { CP_WAIT(0); }
        __syncthreads();

        if (t + 2 < T) {
            int ns = slot - 1; if (ns < 0) ns += NSTAGE;   // (slot+2)%3
            char* st = smem + ns * STAGE_B;
            const int k0 = (t + 2) << 6;
            ld_plane(Ah, rowA, lda, k0, st + 0,       tid);
            ld_plane(Bh, rowB, K,   k0, st + PLANE_B, tid);
            CP_COMMIT();
        }

        char* st = smem + slot * STAGE_B;
        const uint32_t aB = smem_to_u32(st) + (wm * 64) * ASTR_B;
        const uint32_t bB = smem_to_u32(st) + PLANE_B + (wn * 32) * ASTR_B;

#pragma unroll
        for (int s = 0; s < 4; s++) {
            const int koff = s * 32;
            uint32_t ahi[4][4];
#pragma unroll
            for (int mt = 0; mt < 4; mt++) {
                uint32_t addr = aB + (mt * 16 + a_r) * ASTR_B + a_c + koff;
                LDSM_X4(ahi[mt], addr);
            }
#pragma unroll
            for (int np = 0; np < 2; np++) {
                uint32_t baddr = bB + (np * 16 + b_r) * ASTR_B + b_c + koff;
                uint32_t bh[4];
                LDSM_X4(bh, baddr);
#pragma unroll
                for (int mt = 0; mt < 4; mt++) {
                    mma16816(acc[mt][np * 2 + 0], ahi[mt], bh + 0);
                    mma16816(acc[mt][np * 2 + 1], ahi[mt], bh + 2);
                }
            }
        }
        slot++; if (slot == NSTAGE) slot = 0;
    }

#pragma unroll
    for (int mt = 0; mt < 4; mt++) {
#pragma unroll
        for (int half = 0; half < 2; half++) {
            int gr = blockIdx.y * 128 + wm * 64 + mt * 16 + g + half * 8;
            float* crow = Cz + (size_t)gr * Nc;
#pragma unroll
            for (int nt = 0; nt < 4; nt++) {
                int gc = blockIdx.x * 128 + wn * 32 + nt * 8 + tg * 2;
                if (gc + 1 < Nc) {
                    crow[gc]     = acc[mt][nt][half * 2 + 0];
                    crow[gc + 1] = acc[mt][nt][half * 2 + 1];
                }
            }
        }
    }
}

// ---------------------------------------------------------------------------
// prep kernels
// ---------------------------------------------------------------------------
__global__ __launch_bounds__(256) void convert_rows_kernel(
    const float* __restrict__ in, __half* __restrict__ hi, size_t n4)
{
    size_t i = (size_t)blockIdx.x * blockDim.x + threadIdx.x;
    if (i >= n4) return;
    float4 v = ((const float4*)in)[i];
    ((__half2*)hi)[i * 2 + 0] = __halves2half2(__float2half(v.x), __float2half(v.y));
    ((__half2*)hi)[i * 2 + 1] = __halves2half2(__float2half(v.z), __float2half(v.w));
}

__global__ void transpose_h_kernel(
    const float* __restrict__ W, __half* __restrict__ bh, int Ktot, int koff, int Nv)
{
    __shared__ float t[32][33];
    const int n0 = blockIdx.x * 32, k0 = blockIdx.y * 32;
    const int tx = threadIdx.x, ty = threadIdx.y;
#pragma unroll
    for (int i = 0; i < 32; i += 8) {
        int n = n0 + tx;
        t[ty + i][tx] = (n < Nv) ? W[(size_t)(k0 + ty + i) * Nv + n] : 0.f;
    }
    __syncthreads();
#pragma unroll
    for (int i = 0; i < 32; i += 8) {
        int n = n0 + ty + i, k = k0 + tx;
        bh[(size_t)n * Ktot + koff + k] = __float2half(t[tx][ty + i]);
    }
}

// ---------------------------------------------------------------------------
// Depthwise conv1d (D_CONV=4) + SiLU, smem-tiled: block = 32 l x 64 e.
// ---------------------------------------------------------------------------
__global__ __launch_bounds__(256) void conv_silu_kernel(
    const float* __restrict__ cwf, const float* __restrict__ cbf,
    const float* __restrict__ cwb, const float* __restrict__ cbb)
{
    __shared__ float s[35][64];

    const int dir = blockIdx.x >> 5;
    const int e0  = (blockIdx.x & 31) * 64;
    const int l0  = blockIdx.y * 32;
    const int b   = blockIdx.z;
    const int tid = threadIdx.x;

    const float* cw = dir ? cwb : cwf;
    const float* cb = dir ? cbb : cbf;

    const int lbase = dir ? l0 : (l0 - 3);
    for (int i = tid; i < 35 * 64; i += 256) {
        int r = i >> 6;
        int c = i & 63;
        int l = lbase + r;
        float v = 0.f;
        if (l >= 0 && l < L_SEQ)
            v = g_xz[(size_t)(b * L_SEQ + l) * EIGHT_E + dir * 4096 + e0 + c];
        s[r][c] = v;
    }
    __syncthreads();

    const int c  = tid & 63;
    const int r0 = (tid >> 6) * 8;
    const int e  = e0 + c;

    float w0 = cw[e * 4 + (dir ? 3 : 0)];
    float w1 = cw[e * 4 + (dir ? 2 : 1)];
    float w2 = cw[e * 4 + (dir ? 1 : 2)];
    float w3 = cw[e * 4 + (dir ? 0 : 3)];
    const float bias = cb[e];

#pragma unroll
    for (int j = 0; j < 8; j++) {
        const int lr = r0 + j;
        float acc = bias;
        acc = fmaf(s[lr + 0][c], w0, acc);
        acc = fmaf(s[lr + 1][c], w1, acc);
        acc = fmaf(s[lr + 2][c], w2, acc);
        acc = fmaf(s[lr + 3][c], w3, acc);
        float v = acc / (1.f + __expf(-acc));
        size_t idx = (size_t)(b * L_SEQ + l0 + lr) * FOUR_E + dir * E_DIM + e;
        g_xi[idx] = v;
        g_xihi[idx] = __float2half(v);
    }
}

// ---------------------------------------------------------------------------
// delta = softplus( proj[:, :64] @ dt_w + dt_b );  16 m-rows per block (FFMA).
// ---------------------------------------------------------------------------
__device__ __forceinline__ float softplusf(float x)
{
    return (x > 20.f) ? x : log1pf(__expf(x));
}

__global__ __launch_bounds__(256) void delta_kernel(
    const float* __restrict__ dtw_f, const float* __restrict__ dtb_f,
    const float* __restrict__ dtw_b, const float* __restrict__ dtb_b)
{
    __shared__ float s[16][DT_RANK];
    const int dir = blockIdx.z;
    const float* dtw = dir ? dtw_b : dtw_f;
    const float* dtb = dir ? dtb_b : dtb_f;
    const int m0 = blockIdx.y * 16;
    const int col = blockIdx.x * 1024 + threadIdx.x * 4;

    const float* pbase = g_proj + (size_t)dir * M_ROWS * PROJ_N;
#pragma unroll
    for (int i = threadIdx.x; i < 16 * DT_RANK; i += 256) {
        int row = i >> 6, r = i & 63;
        s[row][r] = pbase[(size_t)(m0 + row) * PROJ_N + r];
    }
    __syncthreads();

    float4 bias = *(const float4*)(dtb + col);
    float4 acc[16];
#pragma unroll
    for (int row = 0; row < 16; row++) acc[row] = bias;

#pragma unroll 2
    for (int r = 0; r < DT_RANK; r++) {
        float4 w = *(const float4*)(dtw + (size_t)r * E_DIM + col);
#pragma unroll
        for (int row = 0; row < 16; row++) {
            float sv = s[row][r];
            acc[row].x = fmaf(sv, w.x, acc[row].x);
            acc[row].y = fmaf(sv, w.y, acc[row].y);
            acc[row].z = fmaf(sv, w.z, acc[row].z);
            acc[row].w = fmaf(sv, w.w, acc[row].w);
        }
    }
#pragma unroll
    for (int row = 0; row < 16; row++) {
        float4 o;
        o.x = softplusf(acc[row].x);
        o.y = softplusf(acc[row].y);
        o.z = softplusf(acc[row].z);
        o.w = softplusf(acc[row].w);
        *(float4*)(g_delta + (size_t)(m0 + row) * FOUR_E + dir * E_DIM + col) = o;
    }
}

// ---------------------------------------------------------------------------
// Selective scan + fused output gating: 4 lanes/chain, 8 chains/warp.
// Depth-4 software-pipelined loads (d/u/z/B/C register ring) so the serial
// chain's load latency (~234+ cyc L2) is covered by ~4 steps of work.
// Arithmetic identical to R15 (bit-exact).
// ---------------------------------------------------------------------------
__global__ __launch_bounds__(256) void scan_kernel(
    const float* __restrict__ Alog_f, const float* __restrict__ Alog_b,
    const float* __restrict__ Dp_f,  const float* __restrict__ Dp_b)
{
    const int lane = threadIdx.x & 31;
    const int wglob = blockIdx.x * 8 + (threadIdx.x >> 5);
    const int t = lane & 3;
    const int chain = wglob * 8 + (lane >> 2);
    const int dir = chain >> 13;
    const int b = (chain >> 11) & 3;
    const int e = chain & (E_DIM - 1);
    const int col = dir * E_DIM + e;
    const int n0 = t * 4;

    const float* Al = dir ? Alog_b : Alog_f;
    const float Dpe = (dir ? Dp_b : Dp_f)[e];
    float a[4];
#pragma unroll
    for (int j = 0; j < 4; j++) a[j] = -__expf(Al[e * N_ST + n0 + j]);
    const float a0 = __shfl_sync(0xffffffffu, a[0], lane & ~3);

    bool ok = true;
#pragma unroll
    for (int j = 0; j < 4; j++) {
        float expect = (float)(n0 + j + 1) * a0;
        ok = ok && (fabsf(a[j] - expect) <= 1e-5f * fmaxf(fabsf(a[j]), 1e-20f));
    }
    const bool fast = __all_sync(0xffffffffu, ok);

    const int l0 = dir ? (L_SEQ - 1) : 0;
    const ptrdiff_t strideE = dir ? -FOUR_E : FOUR_E;
    const ptrdiff_t strideZ = dir ? -EIGHT_E : EIGHT_E;
    const ptrdiff_t strideP = dir ? -PROJ_N : PROJ_N;

    const float* dp = g_delta + (size_t)(b * L_SEQ + l0) * FOUR_E + col;
    const float* up = g_xi    + (size_t)(b * L_SEQ + l0) * FOUR_E + col;
    const float* zp = g_xz    + (size_t)(b * L_SEQ + l0) * EIGHT_E + dir * 4096 + 2048 + e;
    const float* pp = g_proj  + (size_t)dir * M_ROWS * PROJ_N
                             + (size_t)(b * L_SEQ + l0) * PROJ_N;
    __half*      yp = g_yhi   + (size_t)(b * L_SEQ + l0) * FOUR_E + col;

    float h0 = 0.f, h1 = 0.f, h2 = 0.f, h3 = 0.f;

    // prologue: prefetch steps 0..3 into slots 0..3
    float  d_[4], u_[4], z_[4];
    float4 B_[4], C_[4];
#pragma unroll
    for (int j = 0; j < 4; j++) {
        d_[j] = dp[(ptrdiff_t)j * strideE];
        u_[j] = up[(ptrdiff_t)j * strideE];
        z_[j] = zp[(ptrdiff_t)j * strideZ];
        B_[j] = *(const float4*)(pp + (ptrdiff_t)j * strideP + 64 + n0);
        C_[j] = *(const float4*)(pp + (ptrdiff_t)j * strideP + 80 + n0);
    }

    for (int i = 0; i < L_SEQ; i += 4) {
#pragma unroll
        for (int j = 0; j < 4; j++) {
            const float d  = d_[j];
            const float u  = u_[j];
            const float zv = z_[j];
            const float4 Bv = B_[j];
            const float4 Cv = C_[j];

            // prefetch step i+j+4 into slot j (pointers currently at step i+j)
            if (i + j + 4 < L_SEQ) {
                d_[j] = dp[(ptrdiff_t)4 * strideE];
                u_[j] = up[(ptrdiff_t)4 * strideE];
                z_[j] = zp[(ptrdiff_t)4 * strideZ];
                B_[j] = *(const float4*)(pp + (ptrdiff_t)4 * strideP + 64 + n0);
                C_[j] = *(const float4*)(pp + (ptrdiff_t)4 * strideP + 80 + n0);
            }

            float d0, d1, d2, d3;
            if (fast) {
                float pb = __expf(d * a0);
                float p2 = pb * pb;
                float p4 = p2 * p2;
                float p8 = p4 * p4;
                float sel = (t == 0) ? 1.f : (t == 1) ? p4 : (t == 2) ? p8 : p8 * p4;
                d0 = sel * pb;
                d1 = d0 * pb;
                d2 = d1 * pb;
                d3 = d2 * pb;
            } else {
                d0 = __expf(d * a[0]);
                d1 = __expf(d * a[1]);
                d2 = __expf(d * a[2]);
                d3 = __expf(d * a[3]);
            }

            const float du = d * u;
            h0 = fmaf(d0, h0, du * Bv.x);
            h1 = fmaf(d1, h1, du * Bv.y);
            h2 = fmaf(d2, h2, du * Bv.z);
            h3 = fmaf(d3, h3, du * Bv.w);

            float v = h0 * Cv.x;
            v = fmaf(h1, Cv.y, v);
            v = fmaf(h2, Cv.z, v);
            v = fmaf(h3, Cv.w, v);
            v += __shfl_xor_sync(0xffffffffu, v, 1);
            v += __shfl_xor_sync(0xffffffffu, v, 2);
            if (t == 0) {
                float sz = zv / (1.f + __expf(-zv));
                *yp = __float2half((v + u * Dpe) * sz);
            }

            dp += strideE; up += strideE; zp += strideZ; yp += strideE; pp += strideP;
        }
    }
}

// ---------------------------------------------------------------------------
// Launcher
// ---------------------------------------------------------------------------
extern "C" void kernel_launch(void* const* d_in, const int* in_sizes, int n_in,
                              void* d_out, int out_size)
{
    (void)in_sizes; (void)n_in; (void)out_size;
    const float* x = (const float*)d_in[0];
    float* out = (float*)d_out;

    cudaFuncSetAttribute(hmma_gemm, cudaFuncAttributeMaxDynamicSharedMemorySize, GEMM_SMEM);

    const float* P[2][9];
    for (int dir = 0; dir < 2; dir++)
        for (int j = 0; j < 9; j++)
            P[dir][j] = (const float*)d_in[1 + dir * 9 + j];

    __half *xhi, *xihi, *yhi, *btin, *btxp, *btout;
    float *p_xz, *p_proj;
    cudaGetSymbolAddress((void**)&xhi, g_xhi);
    cudaGetSymbolAddress((void**)&xihi, g_xihi);
    cudaGetSymbolAddress((void**)&yhi, g_yhi);
    cudaGetSymbolAddress((void**)&btin, g_btin);
    cudaGetSymbolAddress((void**)&btxp, g_btxp);
    cudaGetSymbolAddress((void**)&btout, g_btout);
    cudaGetSymbolAddress((void**)&p_xz, g_xz);
    cudaGetSymbolAddress((void**)&p_proj, g_proj);

    // ---- weight prep ----
    transpose_h_kernel<<<dim3(128, 32), dim3(32, 8)>>>(P[0][0], btin, D_MODEL, 0, 4096);
    transpose_h_kernel<<<dim3(128, 32), dim3(32, 8)>>>(
        P[1][0], btin + (size_t)4096 * D_MODEL, D_MODEL, 0, 4096);
    for (int dir = 0; dir < 2; dir++)
        transpose_h_kernel<<<dim3(4, 64), dim3(32, 8)>>>(
            P[dir][3], btxp + (size_t)dir * 128 * E_DIM, E_DIM, 0, PROJ_N);
    transpose_h_kernel<<<dim3(32, 64), dim3(32, 8)>>>(P[0][8], btout, FOUR_E, 0, D_MODEL);
    transpose_h_kernel<<<dim3(32, 64), dim3(32, 8)>>>(P[1][8], btout, FOUR_E, 2048, D_MODEL);

    // ---- convert x to fp16 ----
    {
        size_t n4 = (size_t)M_ROWS * D_MODEL / 4;
        convert_rows_kernel<<<(unsigned)((n4 + 255) / 256), 256>>>(x, xhi, n4);
    }

    // 1) xz = x @ [in_w_f | in_w_b]
    hmma_gemm<<<dim3(EIGHT_E / 128, M_ROWS / 128, 1), 256, GEMM_SMEM>>>(
        xhi, btin, p_xz, D_MODEL, D_MODEL, EIGHT_E, 0, 0, 0);

    // 2) conv + silu, both dirs (smem-tiled)
    conv_silu_kernel<<<dim3(64, L_SEQ / 32, B_SZ), 256>>>(
        P[0][1], P[0][2], P[1][1], P[1][2]);

    // 3) proj: both dirs batched via blockIdx.z
    hmma_gemm<<<dim3(1, M_ROWS / 128, 2), 256, GEMM_SMEM>>>(
        xihi, btxp, p_proj, FOUR_E, E_DIM, PROJ_N,
        (size_t)E_DIM, (size_t)128 * E_DIM, (size_t)M_ROWS * PROJ_N);

    // 4) delta (both dirs, FFMA)
    delta_kernel<<<dim3(2, M_ROWS / 16, 2), 256>>>(P[0][4], P[0][5], P[1][4], P[1][5]);

    // 5) selective scan + fused gating (both dirs), depth-4 pipelined
    scan_kernel<<<256, 256>>>(P[0][6], P[1][6], P[0][7], P[1][7]);

    // 6) out = [y_f | y_b] @ [out_w_f ; out_w_b]
    hmma_gemm<<<dim3(D_MODEL / 128, M_ROWS / 128, 1), 256, GEMM_SMEM>>>(
        yhi, btout, out, FOUR_E, FOUR_E, D_MODEL, 0, 0, 0);
}